// round 4
// baseline (speedup 1.0000x reference)
#include <cuda_runtime.h>
#include <cstdint>

// Problem dims (fixed)
#define TOKENS 8192
#define IN_F   4096
#define OUT_F  4096

constexpr int BM = 128;
constexpr int BN = 128;
constexpr int BK = 128;            // K bytes per stage (4 x k32 substeps)
constexpr int THREADS = 256;       // 8 warps: 2 (M) x 4 (N)
constexpr int NK = IN_F / BK;      // 32
constexpr int SSTRIDE = 144;       // 128 data + 16 pad (conflict-free for STS.128 + LDSM)

constexpr int A_STAGE = BM * SSTRIDE;              // 18432
constexpr int B_STAGE = BN * SSTRIDE;              // 18432
constexpr int STAGE   = A_STAGE + B_STAGE;         // 36864
constexpr int SMEM_TOTAL = 2 * STAGE;              // 73728 (double buffered)

// Scratch: packed int8 operands (harness delivers int32-widened values)
__device__ int8_t g_packedX[(size_t)TOKENS * IN_F];
__device__ int8_t g_packedW[(size_t)OUT_F * IN_F];

// ---------------- pack: int32 -> int8 ----------------
__global__ void __launch_bounds__(256)
pack_kernel(const int* __restrict__ src, uint32_t* __restrict__ dst, int n_words)
{
    int i = blockIdx.x * blockDim.x + threadIdx.x;
    if (i >= n_words) return;
    int4 v = ((const int4*)src)[i];
    uint32_t p = (v.x & 0xff) | ((v.y & 0xff) << 8) |
                 ((v.z & 0xff) << 16) | ((uint32_t)v.w << 24);
    dst[i] = p;
}

// ---------------- helpers ----------------
__device__ __forceinline__ uint32_t smem_u32(const void* p) {
    return (uint32_t)__cvta_generic_to_shared(p);
}
__device__ __forceinline__ void cp_async16(uint32_t s, const void* g) {
    asm volatile("cp.async.cg.shared.global [%0], [%1], 16;\n" :: "r"(s), "l"(g) : "memory");
}
__device__ __forceinline__ void ldsm_x4(uint32_t& r0, uint32_t& r1, uint32_t& r2, uint32_t& r3,
                                        uint32_t addr)
{
    asm volatile("ldmatrix.sync.aligned.m8n8.x4.shared.b16 {%0,%1,%2,%3}, [%4];"
                 : "=r"(r0), "=r"(r1), "=r"(r2), "=r"(r3) : "r"(addr));
}

__device__ __forceinline__ float quantize_gelu(int acc, float biasv, float a, float b) {
    float y = fmaf(a, (float)acc, biasv);
    float g = 0.5f * y * (1.0f + erff(y * 0.70710678118654752440f));  // exact GeLU
    int q = __float2int_rn(g * b);                                    // rint (RNE)
    q = max(-128, min(127, q));
    return (float)q;
}

// ---------------- main GEMM + fused epilogue (mma.sync IMMA) ----------------
__global__ void __launch_bounds__(THREADS, 2)
w8a8_gelu_q_kernel(const float* __restrict__ bias,
                   const float* __restrict__ pa,
                   const float* __restrict__ pb,
                   float* __restrict__ out)
{
    extern __shared__ __align__(16) int8_t smem[];
    const uint32_t sbase = smem_u32(smem);

    const int tid    = threadIdx.x;
    const int lane   = tid & 31;
    const int warp   = tid >> 5;
    const int warp_m = warp >> 2;   // 0..1 -> 64 rows each
    const int warp_n = warp & 3;    // 0..3 -> 32 cols each
    const int bm = blockIdx.y;
    const int bn = blockIdx.x;

    const int8_t* gA = g_packedX + (size_t)(bm * BM) * IN_F;
    const int8_t* gB = g_packedW + (size_t)(bn * BN) * IN_F;

    int acc[4][4][4];
#pragma unroll
    for (int i = 0; i < 4; i++)
#pragma unroll
        for (int j = 0; j < 4; j++)
#pragma unroll
            for (int r = 0; r < 4; r++) acc[i][j][r] = 0;

    // ---- ldmatrix fragment base addresses (per thread, per-stage-relative) ----
    // quad decomposition for m8n8.x4: lanes 0-7 -> matrix0 rows, 8-15 -> m1, etc.
    const int quad = lane >> 3;      // 0..3
    const int qr   = lane & 7;       // row within matrix
    const int qlow = quad & 1;       // +8-row group
    const int qhi  = quad >> 1;      // +16-byte k-half

    // A: matrix i covers rows warp_m*64 + i*16 + {0..15}, k {0..31} within substep
    uint32_t aAddr[4];
#pragma unroll
    for (int i = 0; i < 4; i++) {
        int row = warp_m * 64 + i * 16 + qlow * 8 + qr;
        aAddr[i] = sbase + row * SSTRIDE + qhi * 16;
    }
    // B: pair jj covers N-rows warp_n*32 + jj*16 + {0..15}
    uint32_t bAddr[2];
#pragma unroll
    for (int jj = 0; jj < 2; jj++) {
        int row = warp_n * 32 + jj * 16 + qlow * 8 + qr;
        bAddr[jj] = sbase + A_STAGE + row * SSTRIDE + qhi * 16;
    }

    // ---- stage loader: 2048 x 16B chunks over 256 threads = 8/thread ----
    auto load_stage = [&](int buf, int kt) {
        const int k0 = kt * BK;
        const uint32_t aB = sbase + buf * STAGE;
        const uint32_t bB = aB + A_STAGE;
#pragma unroll
        for (int t = 0; t < 4; t++) {             // A: 1024 chunks
            int id  = tid + t * THREADS;
            int row = id >> 3, c = id & 7;
            cp_async16(aB + row * SSTRIDE + c * 16,
                       gA + (size_t)row * IN_F + k0 + c * 16);
        }
#pragma unroll
        for (int t = 0; t < 4; t++) {             // B: 1024 chunks
            int id  = tid + t * THREADS;
            int row = id >> 3, c = id & 7;
            cp_async16(bB + row * SSTRIDE + c * 16,
                       gB + (size_t)row * IN_F + k0 + c * 16);
        }
        asm volatile("cp.async.commit_group;\n" ::: "memory");
    };

    load_stage(0, 0);

    for (int kt = 0; kt < NK; kt++) {
        const int buf = kt & 1;
        if (kt + 1 < NK) {
            load_stage(buf ^ 1, kt + 1);
            asm volatile("cp.async.wait_group 1;\n" ::: "memory");
        } else {
            asm volatile("cp.async.wait_group 0;\n" ::: "memory");
        }
        __syncthreads();

        const uint32_t stageOff = buf * STAGE;

#pragma unroll
        for (int ks = 0; ks < 4; ks++) {
            const uint32_t kOff = stageOff + ks * 32;

            // B fragments: 2 ldmatrix cover all 4 j values
            uint32_t b0[4], b1[4];
            ldsm_x4(b0[0], b0[1], b0[2], b0[3], bAddr[0] + kOff);
            ldsm_x4(b1[0], b1[1], b1[2], b1[3], bAddr[1] + kOff);
            // bfr[j] = {reg0, reg2} (j even in pair) / {reg1, reg3} (j odd)
            uint32_t bf[4][2] = {
                { b0[0], b0[2] }, { b0[1], b0[3] },
                { b1[0], b1[2] }, { b1[1], b1[3] }
            };

#pragma unroll
            for (int i = 0; i < 4; i++) {
                uint32_t a0, a1, a2, a3;
                ldsm_x4(a0, a1, a2, a3, aAddr[i] + kOff);
#pragma unroll
                for (int j = 0; j < 4; j++) {
                    asm volatile(
                        "mma.sync.aligned.m16n8k32.row.col.s32.s8.s8.s32 "
                        "{%0,%1,%2,%3}, {%4,%5,%6,%7}, {%8,%9}, {%0,%1,%2,%3};\n"
                        : "+r"(acc[i][j][0]), "+r"(acc[i][j][1]),
                          "+r"(acc[i][j][2]), "+r"(acc[i][j][3])
                        : "r"(a0), "r"(a1), "r"(a2), "r"(a3),
                          "r"(bf[j][0]), "r"(bf[j][1]));
                }
            }
        }
        __syncthreads();
    }

    // ---- fused epilogue: dequant + bias + exact GeLU + requant, write as f32 ----
    const float a = *pa;
    const float b = *pb;

    const int row_base = bm * BM + warp_m * 64 + (lane >> 2);
    const int col_base = bn * BN + warp_n * 32 + (lane & 3) * 2;

#pragma unroll
    for (int i = 0; i < 4; i++) {
        const int row0 = row_base + i * 16;
#pragma unroll
        for (int j = 0; j < 4; j++) {
            const int col = col_base + j * 8;
            const float b0v = bias[col];
            const float b1v = bias[col + 1];

            float2 v0;
            v0.x = quantize_gelu(acc[i][j][0], b0v, a, b);
            v0.y = quantize_gelu(acc[i][j][1], b1v, a, b);
            *(float2*)&out[(size_t)row0 * OUT_F + col] = v0;

            float2 v1;
            v1.x = quantize_gelu(acc[i][j][2], b0v, a, b);
            v1.y = quantize_gelu(acc[i][j][3], b1v, a, b);
            *(float2*)&out[(size_t)(row0 + 8) * OUT_F + col] = v1;
        }
    }
}

extern "C" void kernel_launch(void* const* d_in, const int* in_sizes, int n_in,
                              void* d_out, int out_size)
{
    const int*   x    = (const int*)  d_in[0];   // int32-widened int8 values
    const int*   w    = (const int*)  d_in[1];
    const float* bias = (const float*)d_in[2];
    const float* a    = (const float*)d_in[3];
    const float* b    = (const float*)d_in[4];
    float* out = (float*)d_out;

    int8_t* pX = nullptr;
    int8_t* pW = nullptr;
    cudaGetSymbolAddress((void**)&pX, g_packedX);
    cudaGetSymbolAddress((void**)&pW, g_packedW);

    {
        int nwx = (TOKENS * IN_F) / 4;
        pack_kernel<<<(nwx + 255) / 256, 256>>>(x, (uint32_t*)pX, nwx);
        int nww = (OUT_F * IN_F) / 4;
        pack_kernel<<<(nww + 255) / 256, 256>>>(w, (uint32_t*)pW, nww);
    }

    cudaFuncSetAttribute(w8a8_gelu_q_kernel,
                         cudaFuncAttributeMaxDynamicSharedMemorySize, SMEM_TOTAL);
    dim3 grid(OUT_F / BN, TOKENS / BM);   // (32, 64)
    w8a8_gelu_q_kernel<<<grid, THREADS, SMEM_TOTAL>>>(bias, a, b, out);
}

// round 5
// speedup vs baseline: 1.3375x; 1.3375x over previous
#include <cuda_runtime.h>
#include <cstdint>

// Problem dims (fixed)
#define TOKENS 8192
#define IN_F   4096
#define OUT_F  4096

constexpr int BM = 256;            // rows 0-127: tensor warps, 128-255: dp4a warps
constexpr int BN = 128;
constexpr int BK = 128;            // K bytes per stage
constexpr int THREADS = 512;       // 16 warps: 8 tensor + 8 simt
constexpr int NK = IN_F / BK;      // 32
constexpr int SSTRIDE = 144;       // 128 data + 16 pad

constexpr int A_STAGE = BM * SSTRIDE;              // 36864
constexpr int B_STAGE = BN * SSTRIDE;              // 18432
constexpr int STAGE   = A_STAGE + B_STAGE;         // 55296
constexpr int SMEM_TOTAL = 2 * STAGE;              // 110592

// simt epilogue staging: 128 rows x 132 words (528B) = 67584 B (aliases stage mem)
constexpr int EPI_ROW_WORDS = 132;

// Scratch: packed int8 operands (harness delivers int32-widened values)
__device__ int8_t g_packedX[(size_t)TOKENS * IN_F];
__device__ int8_t g_packedW[(size_t)OUT_F * IN_F];

// ---------------- pack: int32 -> int8 ----------------
__global__ void __launch_bounds__(256)
pack_kernel(const int* __restrict__ src, uint32_t* __restrict__ dst, int n_words)
{
    int i = blockIdx.x * blockDim.x + threadIdx.x;
    if (i >= n_words) return;
    int4 v = ((const int4*)src)[i];
    uint32_t p = (v.x & 0xff) | ((v.y & 0xff) << 8) |
                 ((v.z & 0xff) << 16) | ((uint32_t)v.w << 24);
    dst[i] = p;
}

// ---------------- helpers ----------------
__device__ __forceinline__ uint32_t smem_u32(const void* p) {
    return (uint32_t)__cvta_generic_to_shared(p);
}
__device__ __forceinline__ void cp_async16(uint32_t s, const void* g) {
    asm volatile("cp.async.cg.shared.global [%0], [%1], 16;\n" :: "r"(s), "l"(g) : "memory");
}
__device__ __forceinline__ void ldsm_x4(uint32_t& r0, uint32_t& r1, uint32_t& r2, uint32_t& r3,
                                        uint32_t addr)
{
    asm volatile("ldmatrix.sync.aligned.m8n8.x4.shared.b16 {%0,%1,%2,%3}, [%4];"
                 : "=r"(r0), "=r"(r1), "=r"(r2), "=r"(r3) : "r"(addr));
}

__device__ __forceinline__ float quantize_gelu(int acc, float biasv, float a, float b) {
    float y = fmaf(a, (float)acc, biasv);
    float g = 0.5f * y * (1.0f + erff(y * 0.70710678118654752440f));  // exact GeLU
    int q = __float2int_rn(g * b);                                    // rint (RNE)
    q = max(-128, min(127, q));
    return (float)q;
}

// ---------------- hybrid GEMM: IMMA warps + DP4A warps ----------------
__global__ void __launch_bounds__(THREADS, 1)
w8a8_hybrid_kernel(const float* __restrict__ bias,
                   const float* __restrict__ pa,
                   const float* __restrict__ pb,
                   float* __restrict__ out)
{
    extern __shared__ __align__(16) int8_t smem[];
    const uint32_t sbase = smem_u32(smem);

    const int tid  = threadIdx.x;
    const int lane = tid & 31;
    const int warp = tid >> 5;
    const int bm = blockIdx.y;
    const int bn = blockIdx.x;

    const int8_t* gA = g_packedX + (size_t)(bm * BM) * IN_F;
    const int8_t* gB = g_packedW + (size_t)(bn * BN) * IN_F;

    // ---- stage loader: A 2048 + B 1024 chunks over 512 threads = 6/thread ----
    auto load_stage = [&](int buf, int kt) {
        const int k0 = kt * BK;
        const uint32_t aB = sbase + buf * STAGE;
        const uint32_t bB = aB + A_STAGE;
#pragma unroll
        for (int t = 0; t < 4; t++) {             // A: 2048 chunks (256 rows x 8)
            int id  = tid + t * THREADS;
            int row = id >> 3, c = id & 7;
            cp_async16(aB + row * SSTRIDE + c * 16,
                       gA + (size_t)row * IN_F + k0 + c * 16);
        }
#pragma unroll
        for (int t = 0; t < 2; t++) {             // B: 1024 chunks (128 rows x 8)
            int id  = tid + t * THREADS;
            int row = id >> 3, c = id & 7;
            cp_async16(bB + row * SSTRIDE + c * 16,
                       gB + (size_t)row * IN_F + k0 + c * 16);
        }
        asm volatile("cp.async.commit_group;\n" ::: "memory");
    };

    // ================= per-role setup =================
    const bool is_tensor = (warp < 8);

    // tensor-warp layout (rows 0-127 of tile): 2 (M) x 4 (N) warps
    const int warp_m = (warp >> 2) & 1;  // 0..1 -> 64 rows
    const int warp_n = warp & 3;         // 0..3 -> 32 cols
    const int quad = lane >> 3;
    const int qr   = lane & 7;
    const int qlow = quad & 1;
    const int qhi  = quad >> 1;

    uint32_t aAddr[4], bAddr[2];
#pragma unroll
    for (int i = 0; i < 4; i++) {
        int row = warp_m * 64 + i * 16 + qlow * 8 + qr;
        aAddr[i] = sbase + row * SSTRIDE + qhi * 16;
    }
#pragma unroll
    for (int jj = 0; jj < 2; jj++) {
        int row = warp_n * 32 + jj * 16 + qlow * 8 + qr;
        bAddr[jj] = sbase + A_STAGE + row * SSTRIDE + qhi * 16;
    }

    int tacc[4][4][4];
#pragma unroll
    for (int i = 0; i < 4; i++)
#pragma unroll
        for (int j = 0; j < 4; j++)
#pragma unroll
            for (int r = 0; r < 4; r++) tacc[i][j][r] = 0;

    // simt-warp layout (rows 128-255): 256 threads, 8x8 strided thread tiles
    const int tid_s = tid - 256;                       // 0..255 for simt warps
    const int tm = tid_s & 15;                         // row offset stride-16
    const int tn = tid_s >> 4;                         // col offset stride-16
    int sacc[8][8];
#pragma unroll
    for (int r = 0; r < 8; r++)
#pragma unroll
        for (int c = 0; c < 8; c++) sacc[r][c] = 0;

    // ================= mainloop =================
    load_stage(0, 0);

    for (int kt = 0; kt < NK; kt++) {
        const int buf = kt & 1;
        if (kt + 1 < NK) {
            load_stage(buf ^ 1, kt + 1);
            asm volatile("cp.async.wait_group 1;\n" ::: "memory");
        } else {
            asm volatile("cp.async.wait_group 0;\n" ::: "memory");
        }
        __syncthreads();

        const uint32_t stageOff = buf * STAGE;

        if (is_tensor) {
#pragma unroll
            for (int ks = 0; ks < 4; ks++) {
                const uint32_t kOff = stageOff + ks * 32;
                uint32_t b0[4], b1[4];
                ldsm_x4(b0[0], b0[1], b0[2], b0[3], bAddr[0] + kOff);
                ldsm_x4(b1[0], b1[1], b1[2], b1[3], bAddr[1] + kOff);
                uint32_t bf[4][2] = {
                    { b0[0], b0[2] }, { b0[1], b0[3] },
                    { b1[0], b1[2] }, { b1[1], b1[3] }
                };
#pragma unroll
                for (int i = 0; i < 4; i++) {
                    uint32_t a0, a1, a2, a3;
                    ldsm_x4(a0, a1, a2, a3, aAddr[i] + kOff);
#pragma unroll
                    for (int j = 0; j < 4; j++) {
                        asm volatile(
                            "mma.sync.aligned.m16n8k32.row.col.s32.s8.s8.s32 "
                            "{%0,%1,%2,%3}, {%4,%5,%6,%7}, {%8,%9}, {%0,%1,%2,%3};\n"
                            : "+r"(tacc[i][j][0]), "+r"(tacc[i][j][1]),
                              "+r"(tacc[i][j][2]), "+r"(tacc[i][j][3])
                            : "r"(a0), "r"(a1), "r"(a2), "r"(a3),
                              "r"(bf[j][0]), "r"(bf[j][1]));
                    }
                }
            }
        } else {
            const int8_t* sA = smem + stageOff;
            const int8_t* sB = smem + stageOff + A_STAGE;
#pragma unroll
            for (int kp = 0; kp < 16; kp++) {          // pairs of k4 (8 bytes)
                int2 Aw[8], Bw[8];
#pragma unroll
                for (int r = 0; r < 8; r++)
                    Aw[r] = *(const int2*)(sA + (128 + tm + 16 * r) * SSTRIDE + kp * 8);
#pragma unroll
                for (int c = 0; c < 8; c++)
                    Bw[c] = *(const int2*)(sB + (tn + 16 * c) * SSTRIDE + kp * 8);
#pragma unroll
                for (int r = 0; r < 8; r++)
#pragma unroll
                    for (int c = 0; c < 8; c++) {
                        sacc[r][c] = __dp4a(Aw[r].x, Bw[c].x, sacc[r][c]);
                        sacc[r][c] = __dp4a(Aw[r].y, Bw[c].y, sacc[r][c]);
                    }
            }
        }
        __syncthreads();
    }

    // ================= epilogue =================
    const float a = *pa;
    const float b = *pb;

    if (is_tensor) {
        const int row_base = bm * BM + warp_m * 64 + (lane >> 2);
        const int col_base = bn * BN + warp_n * 32 + (lane & 3) * 2;
#pragma unroll
        for (int i = 0; i < 4; i++) {
            const int row0 = row_base + i * 16;
#pragma unroll
            for (int j = 0; j < 4; j++) {
                const int col = col_base + j * 8;
                const float b0v = bias[col];
                const float b1v = bias[col + 1];
                float2 v0;
                v0.x = quantize_gelu(tacc[i][j][0], b0v, a, b);
                v0.y = quantize_gelu(tacc[i][j][1], b1v, a, b);
                *(float2*)&out[(size_t)row0 * OUT_F + col] = v0;
                float2 v1;
                v1.x = quantize_gelu(tacc[i][j][2], b0v, a, b);
                v1.y = quantize_gelu(tacc[i][j][3], b1v, a, b);
                *(float2*)&out[(size_t)(row0 + 8) * OUT_F + col] = v1;
            }
        }
    } else {
        // stage quantized values into smem for coalesced stores
        float* epi = (float*)smem;
#pragma unroll
        for (int r = 0; r < 8; r++) {
            const int srow = tm + 16 * r;
#pragma unroll
            for (int c = 0; c < 8; c++) {
                const int scol = tn + 16 * c;
                const float bv = bias[bn * BN + scol];
                epi[srow * EPI_ROW_WORDS + scol] = quantize_gelu(sacc[r][c], bv, a, b);
            }
        }
    }
    __syncthreads();

    // cooperative coalesced store of simt rows (all 512 threads)
    {
        const float* epi = (const float*)smem;
        const int rr = tid >> 2;          // 0..127
        const int c4 = tid & 3;           // 0..3
        float* dst = &out[(size_t)(bm * BM + 128 + rr) * OUT_F + bn * BN];
#pragma unroll
        for (int j = 0; j < 8; j++) {
            const int cw = (c4 + 4 * j) * 4;   // float column
            const float* s = &epi[rr * EPI_ROW_WORDS + cw];
            float4 v = make_float4(s[0], s[1], s[2], s[3]);
            *(float4*)&dst[cw] = v;
        }
    }
}

extern "C" void kernel_launch(void* const* d_in, const int* in_sizes, int n_in,
                              void* d_out, int out_size)
{
    const int*   x    = (const int*)  d_in[0];   // int32-widened int8 values
    const int*   w    = (const int*)  d_in[1];
    const float* bias = (const float*)d_in[2];
    const float* a    = (const float*)d_in[3];
    const float* b    = (const float*)d_in[4];
    float* out = (float*)d_out;

    int8_t* pX = nullptr;
    int8_t* pW = nullptr;
    cudaGetSymbolAddress((void**)&pX, g_packedX);
    cudaGetSymbolAddress((void**)&pW, g_packedW);

    {
        int nwx = (TOKENS * IN_F) / 4;
        pack_kernel<<<(nwx + 255) / 256, 256>>>(x, (uint32_t*)pX, nwx);
        int nww = (OUT_F * IN_F) / 4;
        pack_kernel<<<(nww + 255) / 256, 256>>>(w, (uint32_t*)pW, nww);
    }

    cudaFuncSetAttribute(w8a8_hybrid_kernel,
                         cudaFuncAttributeMaxDynamicSharedMemorySize, SMEM_TOTAL);
    dim3 grid(OUT_F / BN, TOKENS / BM);   // (32, 32)
    w8a8_hybrid_kernel<<<grid, THREADS, SMEM_TOTAL>>>(bias, a, b, out);
}

// round 6
// speedup vs baseline: 1.3666x; 1.0217x over previous
#include <cuda_runtime.h>
#include <cstdint>

// Problem dims (fixed)
#define TOKENS 8192
#define IN_F   4096
#define OUT_F  4096

constexpr int BM = 256;            // 144 tensor rows + 112 simt rows
constexpr int BN = 128;
constexpr int BK = 128;            // K bytes per stage
constexpr int THREADS = 512;       // warps 0-7 tensor, 8-15 simt
constexpr int NK = IN_F / BK;      // 32
constexpr int SSTRIDE = 144;       // 128 data + 16 pad

constexpr int RT = 144;            // tensor rows (wm0: 80, wm1: 64)
constexpr int RS = 112;            // simt rows

constexpr int T_A = RT * SSTRIDE;            // 20736
constexpr int T_B = BN * SSTRIDE;            // 18432
constexpr int T_STAGE = T_A + T_B;           // 39168
constexpr int S_A = RS * SSTRIDE;            // 16128
constexpr int S_B = BN * SSTRIDE;            // 18432
constexpr int S_STAGE = S_A + S_B;           // 34560
constexpr int SIMT_BASE = 2 * T_STAGE;       // 78336
constexpr int SMEM_TOTAL = SIMT_BASE + 2 * S_STAGE;  // 147456

constexpr int EPI_ROW_WORDS = 132;           // simt staging row stride (floats)

// Scratch: packed int8 operands (harness delivers int32-widened values)
__device__ int8_t g_packedX[(size_t)TOKENS * IN_F];
__device__ int8_t g_packedW[(size_t)OUT_F * IN_F];

// ---------------- pack: int32 -> int8 ----------------
__global__ void __launch_bounds__(256)
pack_kernel(const int* __restrict__ src, uint32_t* __restrict__ dst, int n_words)
{
    int i = blockIdx.x * blockDim.x + threadIdx.x;
    if (i >= n_words) return;
    int4 v = ((const int4*)src)[i];
    uint32_t p = (v.x & 0xff) | ((v.y & 0xff) << 8) |
                 ((v.z & 0xff) << 16) | ((uint32_t)v.w << 24);
    dst[i] = p;
}

// ---------------- helpers ----------------
__device__ __forceinline__ uint32_t smem_u32(const void* p) {
    return (uint32_t)__cvta_generic_to_shared(p);
}
__device__ __forceinline__ void cp_async16(uint32_t s, const void* g) {
    asm volatile("cp.async.cg.shared.global [%0], [%1], 16;\n" :: "r"(s), "l"(g) : "memory");
}
__device__ __forceinline__ void ldsm_x4(uint32_t& r0, uint32_t& r1, uint32_t& r2, uint32_t& r3,
                                        uint32_t addr)
{
    asm volatile("ldmatrix.sync.aligned.m8n8.x4.shared.b16 {%0,%1,%2,%3}, [%4];"
                 : "=r"(r0), "=r"(r1), "=r"(r2), "=r"(r3) : "r"(addr));
}
#define BAR_T() asm volatile("bar.sync 1, 256;" ::: "memory")
#define BAR_S() asm volatile("bar.sync 2, 256;" ::: "memory")
#define CP_COMMIT() asm volatile("cp.async.commit_group;\n" ::: "memory")
#define CP_WAIT1() asm volatile("cp.async.wait_group 1;\n" ::: "memory")
#define CP_WAIT0() asm volatile("cp.async.wait_group 0;\n" ::: "memory")

__device__ __forceinline__ float quantize_gelu(int acc, float biasv, float a, float b) {
    float y = fmaf(a, (float)acc, biasv);
    float g = 0.5f * y * (1.0f + erff(y * 0.70710678118654752440f));  // exact GeLU
    int q = __float2int_rn(g * b);                                    // rint (RNE)
    q = max(-128, min(127, q));
    return (float)q;
}

// ---------------- hybrid GEMM: decoupled IMMA + DP4A pipelines ----------------
__global__ void __launch_bounds__(THREADS, 1)
w8a8_hybrid_kernel(const float* __restrict__ bias,
                   const float* __restrict__ pa,
                   const float* __restrict__ pb,
                   float* __restrict__ out)
{
    extern __shared__ __align__(16) int8_t smem[];
    const uint32_t sbase = smem_u32(smem);

    const int tid  = threadIdx.x;
    const int lane = tid & 31;
    const int warp = tid >> 5;
    const int bm = blockIdx.y;
    const int bn = blockIdx.x;

    const float a = *pa;
    const float b = *pb;

    const int8_t* gB = g_packedW + (size_t)(bn * BN) * IN_F;

    if (warp < 8) {
        // ================= TENSOR class: rows 0..143 =================
        const int ttid = tid;                     // 0..255
        const int warp_m = (warp >> 2) & 1;       // 0: 80 rows (5 tiles), 1: 64 rows (4 tiles)
        const int warp_n = warp & 3;
        const int ni = 5 - warp_m;
        const int quad = lane >> 3;
        const int qr   = lane & 7;
        const int qlow = quad & 1;
        const int qhi  = quad >> 1;

        const int8_t* gA = g_packedX + (size_t)(bm * BM) * IN_F;

        uint32_t aAddr[5], bAddr[2];
#pragma unroll
        for (int i = 0; i < 5; i++) {
            int row = warp_m * 80 + i * 16 + qlow * 8 + qr;
            aAddr[i] = sbase + row * SSTRIDE + qhi * 16;
        }
#pragma unroll
        for (int jj = 0; jj < 2; jj++) {
            int row = warp_n * 32 + jj * 16 + qlow * 8 + qr;
            bAddr[jj] = sbase + T_A + row * SSTRIDE + qhi * 16;
        }

        int acc[5][4][4];
#pragma unroll
        for (int i = 0; i < 5; i++)
#pragma unroll
            for (int j = 0; j < 4; j++)
#pragma unroll
                for (int r = 0; r < 4; r++) acc[i][j][r] = 0;

        auto load_t = [&](int buf, int kt) {
            const int k0 = kt * BK;
            const uint32_t aB = sbase + buf * T_STAGE;
            const uint32_t bB = aB + T_A;
#pragma unroll
            for (int t = 0; t < 5; t++) {            // A: 1152 chunks (144 rows x 8)
                int id = ttid + t * 256;
                if (id < RT * 8) {
                    int row = id >> 3, c = id & 7;
                    cp_async16(aB + row * SSTRIDE + c * 16,
                               gA + (size_t)row * IN_F + k0 + c * 16);
                }
            }
#pragma unroll
            for (int t = 0; t < 4; t++) {            // B: 1024 chunks
                int id = ttid + t * 256;
                int row = id >> 3, c = id & 7;
                cp_async16(bB + row * SSTRIDE + c * 16,
                           gB + (size_t)row * IN_F + k0 + c * 16);
            }
            CP_COMMIT();
        };

        load_t(0, 0);

        for (int kt = 0; kt < NK; kt++) {
            const int buf = kt & 1;
            if (kt + 1 < NK) { load_t(buf ^ 1, kt + 1); CP_WAIT1(); }
            else             { CP_WAIT0(); }
            BAR_T();

            const uint32_t stageOff = buf * T_STAGE;
#pragma unroll
            for (int ks = 0; ks < 4; ks++) {
                const uint32_t kOff = stageOff + ks * 32;
                uint32_t b0[4], b1[4];
                ldsm_x4(b0[0], b0[1], b0[2], b0[3], bAddr[0] + kOff);
                ldsm_x4(b1[0], b1[1], b1[2], b1[3], bAddr[1] + kOff);
                uint32_t bf[4][2] = {
                    { b0[0], b0[2] }, { b0[1], b0[3] },
                    { b1[0], b1[2] }, { b1[1], b1[3] }
                };
#pragma unroll
                for (int i = 0; i < 5; i++) {
                    if (i < ni) {
                        uint32_t a0, a1, a2, a3;
                        ldsm_x4(a0, a1, a2, a3, aAddr[i] + kOff);
#pragma unroll
                        for (int j = 0; j < 4; j++) {
                            asm volatile(
                                "mma.sync.aligned.m16n8k32.row.col.s32.s8.s8.s32 "
                                "{%0,%1,%2,%3}, {%4,%5,%6,%7}, {%8,%9}, {%0,%1,%2,%3};\n"
                                : "+r"(acc[i][j][0]), "+r"(acc[i][j][1]),
                                  "+r"(acc[i][j][2]), "+r"(acc[i][j][3])
                                : "r"(a0), "r"(a1), "r"(a2), "r"(a3),
                                  "r"(bf[j][0]), "r"(bf[j][1]));
                        }
                    }
                }
            }
            BAR_T();
        }

        // tensor epilogue
        const int row_base = bm * BM + warp_m * 80 + (lane >> 2);
        const int col_base = bn * BN + warp_n * 32 + (lane & 3) * 2;
#pragma unroll
        for (int i = 0; i < 5; i++) {
            if (i < ni) {
                const int row0 = row_base + i * 16;
#pragma unroll
                for (int j = 0; j < 4; j++) {
                    const int col = col_base + j * 8;
                    const float b0v = bias[col];
                    const float b1v = bias[col + 1];
                    float2 v0;
                    v0.x = quantize_gelu(acc[i][j][0], b0v, a, b);
                    v0.y = quantize_gelu(acc[i][j][1], b1v, a, b);
                    *(float2*)&out[(size_t)row0 * OUT_F + col] = v0;
                    float2 v1;
                    v1.x = quantize_gelu(acc[i][j][2], b0v, a, b);
                    v1.y = quantize_gelu(acc[i][j][3], b1v, a, b);
                    *(float2*)&out[(size_t)(row0 + 8) * OUT_F + col] = v1;
                }
            }
        }
    } else {
        // ================= SIMT class: rows 144..255 =================
        const int stid = tid - 256;               // 0..255
        const int tm = stid & 15;                 // row offset, stride 16 (7 tiles)
        const int tn = stid >> 4;                 // col offset, stride 16 (8 tiles)

        const int8_t* gA = g_packedX + (size_t)(bm * BM + RT) * IN_F;

        int acc[7][8];
#pragma unroll
        for (int r = 0; r < 7; r++)
#pragma unroll
            for (int c = 0; c < 8; c++) acc[r][c] = 0;

        auto load_s = [&](int buf, int kt) {
            const int k0 = kt * BK;
            const uint32_t aB = sbase + SIMT_BASE + buf * S_STAGE;
            const uint32_t bB = aB + S_A;
#pragma unroll
            for (int t = 0; t < 4; t++) {            // A: 896 chunks (112 rows x 8)
                int id = stid + t * 256;
                if (id < RS * 8) {
                    int row = id >> 3, c = id & 7;
                    cp_async16(aB + row * SSTRIDE + c * 16,
                               gA + (size_t)row * IN_F + k0 + c * 16);
                }
            }
#pragma unroll
            for (int t = 0; t < 4; t++) {            // B: 1024 chunks
                int id = stid + t * 256;
                int row = id >> 3, c = id & 7;
                cp_async16(bB + row * SSTRIDE + c * 16,
                           gB + (size_t)row * IN_F + k0 + c * 16);
            }
            CP_COMMIT();
        };

        load_s(0, 0);

        for (int kt = 0; kt < NK; kt++) {
            const int buf = kt & 1;
            if (kt + 1 < NK) { load_s(buf ^ 1, kt + 1); CP_WAIT1(); }
            else             { CP_WAIT0(); }
            BAR_S();

            const int8_t* sA = smem + SIMT_BASE + buf * S_STAGE;
            const int8_t* sB = sA + S_A;
#pragma unroll
            for (int kp = 0; kp < 16; kp++) {
                int2 Bw[8];
#pragma unroll
                for (int c = 0; c < 8; c++)
                    Bw[c] = *(const int2*)(sB + (tn + 16 * c) * SSTRIDE + kp * 8);
#pragma unroll
                for (int r = 0; r < 7; r++) {
                    int2 Aw = *(const int2*)(sA + (tm + 16 * r) * SSTRIDE + kp * 8);
#pragma unroll
                    for (int c = 0; c < 8; c++) {
                        acc[r][c] = __dp4a(Aw.x, Bw[c].x, acc[r][c]);
                        acc[r][c] = __dp4a(Aw.y, Bw[c].y, acc[r][c]);
                    }
                }
            }
            BAR_S();
        }

        // simt epilogue: quantize to smem staging, then coalesced stores
        float* epi = (float*)(smem + SIMT_BASE);
#pragma unroll
        for (int r = 0; r < 7; r++) {
            const int srow = tm + 16 * r;
#pragma unroll
            for (int c = 0; c < 8; c++) {
                const int scol = tn + 16 * c;
                const float bv = bias[bn * BN + scol];
                epi[srow * EPI_ROW_WORDS + scol] = quantize_gelu(acc[r][c], bv, a, b);
            }
        }
        BAR_S();

        // 112 rows x 32 float4 = 3584 stores over 256 threads = 14 each
#pragma unroll
        for (int t = 0; t < 14; t++) {
            int idx = stid + t * 256;
            int row = idx >> 5;
            int c4  = idx & 31;
            const float* s = &epi[row * EPI_ROW_WORDS + c4 * 4];
            float4 v = make_float4(s[0], s[1], s[2], s[3]);
            *(float4*)&out[(size_t)(bm * BM + RT + row) * OUT_F + bn * BN + c4 * 4] = v;
        }
    }
}

extern "C" void kernel_launch(void* const* d_in, const int* in_sizes, int n_in,
                              void* d_out, int out_size)
{
    const int*   x    = (const int*)  d_in[0];   // int32-widened int8 values
    const int*   w    = (const int*)  d_in[1];
    const float* bias = (const float*)d_in[2];
    const float* a    = (const float*)d_in[3];
    const float* b    = (const float*)d_in[4];
    float* out = (float*)d_out;

    int8_t* pX = nullptr;
    int8_t* pW = nullptr;
    cudaGetSymbolAddress((void**)&pX, g_packedX);
    cudaGetSymbolAddress((void**)&pW, g_packedW);

    {
        int nwx = (TOKENS * IN_F) / 4;
        pack_kernel<<<(nwx + 255) / 256, 256>>>(x, (uint32_t*)pX, nwx);
        int nww = (OUT_F * IN_F) / 4;
        pack_kernel<<<(nww + 255) / 256, 256>>>(w, (uint32_t*)pW, nww);
    }

    cudaFuncSetAttribute(w8a8_hybrid_kernel,
                         cudaFuncAttributeMaxDynamicSharedMemorySize, SMEM_TOTAL);
    dim3 grid(OUT_F / BN, TOKENS / BM);   // (32, 32)
    w8a8_hybrid_kernel<<<grid, THREADS, SMEM_TOTAL>>>(bias, a, b, out);
}

// round 7
// speedup vs baseline: 1.5142x; 1.1080x over previous
#include <cuda_runtime.h>
#include <cstdint>

// Problem dims (fixed)
#define TOKENS 8192
#define IN_F   4096
#define OUT_F  4096

constexpr int BM = 256;            // 128 tensor rows + 128 simt rows
constexpr int BN = 128;
constexpr int BK = 128;            // K bytes per stage
constexpr int THREADS = 512;       // warps 0-7 tensor, 8-15 simt
constexpr int NK = IN_F / BK;      // 32
constexpr int SSTRIDE = 144;       // 128 data + 16 pad

constexpr int RT = 128;            // tensor rows
constexpr int RS = 128;            // simt rows

constexpr int T_A = RT * SSTRIDE;            // 18432
constexpr int T_B = BN * SSTRIDE;            // 18432
constexpr int T_STAGE = T_A + T_B;           // 36864
constexpr int S_A = RS * SSTRIDE;            // 18432
constexpr int S_B = BN * SSTRIDE;            // 18432
constexpr int S_STAGE = S_A + S_B;           // 36864
constexpr int SIMT_BASE = 2 * T_STAGE;       // 73728
constexpr int SMEM_TOTAL = SIMT_BASE + 2 * S_STAGE;  // 147456

constexpr int EPI_ROW_WORDS = 132;           // simt staging row stride (floats)

// Scratch: packed int8 operands (harness delivers int32-widened values)
__device__ int8_t g_packedX[(size_t)TOKENS * IN_F];
__device__ int8_t g_packedW[(size_t)OUT_F * IN_F];

// ---------------- pack: int32 -> int8 ----------------
__global__ void __launch_bounds__(256)
pack_kernel(const int* __restrict__ src, uint32_t* __restrict__ dst, int n_words)
{
    int i = blockIdx.x * blockDim.x + threadIdx.x;
    if (i >= n_words) return;
    int4 v = ((const int4*)src)[i];
    uint32_t p = (v.x & 0xff) | ((v.y & 0xff) << 8) |
                 ((v.z & 0xff) << 16) | ((uint32_t)v.w << 24);
    dst[i] = p;
}

// ---------------- helpers ----------------
__device__ __forceinline__ uint32_t smem_u32(const void* p) {
    return (uint32_t)__cvta_generic_to_shared(p);
}
__device__ __forceinline__ void cp_async16(uint32_t s, const void* g) {
    asm volatile("cp.async.cg.shared.global [%0], [%1], 16;\n" :: "r"(s), "l"(g) : "memory");
}
__device__ __forceinline__ void ldsm_x4(uint32_t& r0, uint32_t& r1, uint32_t& r2, uint32_t& r3,
                                        uint32_t addr)
{
    asm volatile("ldmatrix.sync.aligned.m8n8.x4.shared.b16 {%0,%1,%2,%3}, [%4];"
                 : "=r"(r0), "=r"(r1), "=r"(r2), "=r"(r3) : "r"(addr));
}
#define BAR_T() asm volatile("bar.sync 1, 256;" ::: "memory")
#define BAR_S() asm volatile("bar.sync 2, 256;" ::: "memory")
#define CP_COMMIT() asm volatile("cp.async.commit_group;\n" ::: "memory")
#define CP_WAIT1() asm volatile("cp.async.wait_group 1;\n" ::: "memory")
#define CP_WAIT0() asm volatile("cp.async.wait_group 0;\n" ::: "memory")

__device__ __forceinline__ float quantize_gelu(int acc, float biasv, float a, float b) {
    float y = fmaf(a, (float)acc, biasv);
    float g = 0.5f * y * (1.0f + erff(y * 0.70710678118654752440f));  // exact GeLU
    int q = __float2int_rn(g * b);                                    // rint (RNE)
    q = max(-128, min(127, q));
    return (float)q;
}

// ---------------- hybrid GEMM: decoupled IMMA + DP4A pipelines ----------------
__global__ void __launch_bounds__(THREADS, 1)
w8a8_hybrid_kernel(const float* __restrict__ bias,
                   const float* __restrict__ pa,
                   const float* __restrict__ pb,
                   float* __restrict__ out)
{
    extern __shared__ __align__(16) int8_t smem[];
    const uint32_t sbase = smem_u32(smem);

    const int tid  = threadIdx.x;
    const int lane = tid & 31;
    const int warp = tid >> 5;
    const int bm = blockIdx.y;
    const int bn = blockIdx.x;

    const float a = *pa;
    const float b = *pb;

    const int8_t* gB = g_packedW + (size_t)(bn * BN) * IN_F;

    if (warp < 8) {
        // ================= TENSOR class: rows 0..127 =================
        const int ttid = tid;                     // 0..255
        const int warp_m = (warp >> 2) & 1;       // 64 rows each
        const int warp_n = warp & 3;
        const int quad = lane >> 3;
        const int qr   = lane & 7;
        const int qlow = quad & 1;
        const int qhi  = quad >> 1;

        const int8_t* gA = g_packedX + (size_t)(bm * BM) * IN_F;

        uint32_t aAddr[4], bAddr[2];
#pragma unroll
        for (int i = 0; i < 4; i++) {
            int row = warp_m * 64 + i * 16 + qlow * 8 + qr;
            aAddr[i] = sbase + row * SSTRIDE + qhi * 16;
        }
#pragma unroll
        for (int jj = 0; jj < 2; jj++) {
            int row = warp_n * 32 + jj * 16 + qlow * 8 + qr;
            bAddr[jj] = sbase + T_A + row * SSTRIDE + qhi * 16;
        }

        int acc[4][4][4];
#pragma unroll
        for (int i = 0; i < 4; i++)
#pragma unroll
            for (int j = 0; j < 4; j++)
#pragma unroll
                for (int r = 0; r < 4; r++) acc[i][j][r] = 0;

        auto load_t = [&](int buf, int kt) {
            const int k0 = kt * BK;
            const uint32_t aB = sbase + buf * T_STAGE;
            const uint32_t bB = aB + T_A;
#pragma unroll
            for (int t = 0; t < 4; t++) {            // A: 1024 chunks (128 rows x 8)
                int id = ttid + t * 256;
                int row = id >> 3, c = id & 7;
                cp_async16(aB + row * SSTRIDE + c * 16,
                           gA + (size_t)row * IN_F + k0 + c * 16);
            }
#pragma unroll
            for (int t = 0; t < 4; t++) {            // B: 1024 chunks
                int id = ttid + t * 256;
                int row = id >> 3, c = id & 7;
                cp_async16(bB + row * SSTRIDE + c * 16,
                           gB + (size_t)row * IN_F + k0 + c * 16);
            }
            CP_COMMIT();
        };

        load_t(0, 0);

        for (int kt = 0; kt < NK; kt++) {
            const int buf = kt & 1;
            if (kt + 1 < NK) { load_t(buf ^ 1, kt + 1); CP_WAIT1(); }
            else             { CP_WAIT0(); }
            BAR_T();

            const uint32_t stageOff = buf * T_STAGE;
#pragma unroll
            for (int ks = 0; ks < 4; ks++) {
                const uint32_t kOff = stageOff + ks * 32;
                uint32_t b0[4], b1[4];
                ldsm_x4(b0[0], b0[1], b0[2], b0[3], bAddr[0] + kOff);
                ldsm_x4(b1[0], b1[1], b1[2], b1[3], bAddr[1] + kOff);
                uint32_t bf[4][2] = {
                    { b0[0], b0[2] }, { b0[1], b0[3] },
                    { b1[0], b1[2] }, { b1[1], b1[3] }
                };
#pragma unroll
                for (int i = 0; i < 4; i++) {
                    uint32_t a0, a1, a2, a3;
                    ldsm_x4(a0, a1, a2, a3, aAddr[i] + kOff);
#pragma unroll
                    for (int j = 0; j < 4; j++) {
                        asm volatile(
                            "mma.sync.aligned.m16n8k32.row.col.s32.s8.s8.s32 "
                            "{%0,%1,%2,%3}, {%4,%5,%6,%7}, {%8,%9}, {%0,%1,%2,%3};\n"
                            : "+r"(acc[i][j][0]), "+r"(acc[i][j][1]),
                              "+r"(acc[i][j][2]), "+r"(acc[i][j][3])
                            : "r"(a0), "r"(a1), "r"(a2), "r"(a3),
                              "r"(bf[j][0]), "r"(bf[j][1]));
                    }
                }
            }
            BAR_T();
        }

        // tensor epilogue
        const int row_base = bm * BM + warp_m * 64 + (lane >> 2);
        const int col_base = bn * BN + warp_n * 32 + (lane & 3) * 2;
#pragma unroll
        for (int i = 0; i < 4; i++) {
            const int row0 = row_base + i * 16;
#pragma unroll
            for (int j = 0; j < 4; j++) {
                const int col = col_base + j * 8;
                const float b0v = bias[col];
                const float b1v = bias[col + 1];
                float2 v0;
                v0.x = quantize_gelu(acc[i][j][0], b0v, a, b);
                v0.y = quantize_gelu(acc[i][j][1], b1v, a, b);
                *(float2*)&out[(size_t)row0 * OUT_F + col] = v0;
                float2 v1;
                v1.x = quantize_gelu(acc[i][j][2], b0v, a, b);
                v1.y = quantize_gelu(acc[i][j][3], b1v, a, b);
                *(float2*)&out[(size_t)(row0 + 8) * OUT_F + col] = v1;
            }
        }
    } else {
        // ================= SIMT class: rows 128..255 =================
        const int stid = tid - 256;               // 0..255
        const int tm = stid & 15;                 // row offset, stride 16 (8 tiles)
        const int tn = stid >> 4;                 // col offset, stride 16 (8 tiles)

        const int8_t* gA = g_packedX + (size_t)(bm * BM + RT) * IN_F;

        int acc[8][8];
#pragma unroll
        for (int r = 0; r < 8; r++)
#pragma unroll
            for (int c = 0; c < 8; c++) acc[r][c] = 0;

        auto load_s = [&](int buf, int kt) {
            const int k0 = kt * BK;
            const uint32_t aB = sbase + SIMT_BASE + buf * S_STAGE;
            const uint32_t bB = aB + S_A;
#pragma unroll
            for (int t = 0; t < 4; t++) {            // A: 1024 chunks (128 rows x 8)
                int id = stid + t * 256;
                int row = id >> 3, c = id & 7;
                cp_async16(aB + row * SSTRIDE + c * 16,
                           gA + (size_t)row * IN_F + k0 + c * 16);
            }
#pragma unroll
            for (int t = 0; t < 4; t++) {            // B: 1024 chunks
                int id = stid + t * 256;
                int row = id >> 3, c = id & 7;
                cp_async16(bB + row * SSTRIDE + c * 16,
                           gB + (size_t)row * IN_F + k0 + c * 16);
            }
            CP_COMMIT();
        };

        load_s(0, 0);

        for (int kt = 0; kt < NK; kt++) {
            const int buf = kt & 1;
            if (kt + 1 < NK) { load_s(buf ^ 1, kt + 1); CP_WAIT1(); }
            else             { CP_WAIT0(); }
            BAR_S();

            const int8_t* sA = smem + SIMT_BASE + buf * S_STAGE;
            const int8_t* sB = sA + S_A;
#pragma unroll
            for (int kp = 0; kp < 16; kp++) {
                int2 Bw[8];
#pragma unroll
                for (int c = 0; c < 8; c++)
                    Bw[c] = *(const int2*)(sB + (tn + 16 * c) * SSTRIDE + kp * 8);
#pragma unroll
                for (int r = 0; r < 8; r++) {
                    int2 Aw = *(const int2*)(sA + (tm + 16 * r) * SSTRIDE + kp * 8);
#pragma unroll
                    for (int c = 0; c < 8; c++) {
                        acc[r][c] = __dp4a(Aw.x, Bw[c].x, acc[r][c]);
                        acc[r][c] = __dp4a(Aw.y, Bw[c].y, acc[r][c]);
                    }
                }
            }
            BAR_S();
        }

        // simt epilogue: quantize to smem staging, then coalesced stores
        float* epi = (float*)(smem + SIMT_BASE);
#pragma unroll
        for (int r = 0; r < 8; r++) {
            const int srow = tm + 16 * r;
#pragma unroll
            for (int c = 0; c < 8; c++) {
                const int scol = tn + 16 * c;
                const float bv = bias[bn * BN + scol];
                epi[srow * EPI_ROW_WORDS + scol] = quantize_gelu(acc[r][c], bv, a, b);
            }
        }
        BAR_S();

        // 128 rows x 32 float4 = 4096 stores over 256 threads = 16 each
#pragma unroll
        for (int t = 0; t < 16; t++) {
            int idx = stid + t * 256;
            int row = idx >> 5;
            int c4  = idx & 31;
            const float* s = &epi[row * EPI_ROW_WORDS + c4 * 4];
            float4 v = make_float4(s[0], s[1], s[2], s[3]);
            *(float4*)&out[(size_t)(bm * BM + RT + row) * OUT_F + bn * BN + c4 * 4] = v;
        }
    }
}

extern "C" void kernel_launch(void* const* d_in, const int* in_sizes, int n_in,
                              void* d_out, int out_size)
{
    const int*   x    = (const int*)  d_in[0];   // int32-widened int8 values
    const int*   w    = (const int*)  d_in[1];
    const float* bias = (const float*)d_in[2];
    const float* a    = (const float*)d_in[3];
    const float* b    = (const float*)d_in[4];
    float* out = (float*)d_out;

    int8_t* pX = nullptr;
    int8_t* pW = nullptr;
    cudaGetSymbolAddress((void**)&pX, g_packedX);
    cudaGetSymbolAddress((void**)&pW, g_packedW);

    {
        int nwx = (TOKENS * IN_F) / 4;
        pack_kernel<<<(nwx + 255) / 256, 256>>>(x, (uint32_t*)pX, nwx);
        int nww = (OUT_F * IN_F) / 4;
        pack_kernel<<<(nww + 255) / 256, 256>>>(w, (uint32_t*)pW, nww);
    }

    cudaFuncSetAttribute(w8a8_hybrid_kernel,
                         cudaFuncAttributeMaxDynamicSharedMemorySize, SMEM_TOTAL);
    dim3 grid(OUT_F / BN, TOKENS / BM);   // (32, 32)
    w8a8_hybrid_kernel<<<grid, THREADS, SMEM_TOTAL>>>(bias, a, b, out);
}

// round 9
// speedup vs baseline: 1.5709x; 1.0375x over previous
#include <cuda_runtime.h>
#include <cstdint>

// Problem dims (fixed)
#define TOKENS 8192
#define IN_F   4096
#define OUT_F  4096

constexpr int BM = 256;            // 128 tensor rows + 128 simt rows
constexpr int BN = 128;
constexpr int BK = 128;            // K bytes per stage
constexpr int THREADS = 512;       // warps 0-7 tensor, 8-15 simt
constexpr int NK = IN_F / BK;      // 32
constexpr int SSTRIDE = 144;       // 128 data + 16 pad
constexpr int NSTAGE = 3;

constexpr int RT = 128;            // tensor rows
constexpr int RS = 128;            // simt rows

constexpr int T_A = RT * SSTRIDE;            // 18432
constexpr int T_B = BN * SSTRIDE;            // 18432
constexpr int T_STAGE = T_A + T_B;           // 36864
constexpr int S_A = RS * SSTRIDE;            // 18432
constexpr int S_B = BN * SSTRIDE;            // 18432
constexpr int S_STAGE = S_A + S_B;           // 36864
constexpr int SIMT_BASE = NSTAGE * T_STAGE;              // 110592
constexpr int SMEM_TOTAL = SIMT_BASE + NSTAGE * S_STAGE; // 221184

constexpr int EPI_ROW_WORDS = 132;           // simt staging row stride (floats)

// Scratch: packed int8 operands (harness delivers int32-widened values)
__device__ int8_t g_packedX[(size_t)TOKENS * IN_F];
__device__ int8_t g_packedW[(size_t)OUT_F * IN_F];

// ---------------- fused pack: int32 -> int8 for both operands ----------------
// One output word per thread; explicit per-array word counts (X: nx, W: nw).
__global__ void __launch_bounds__(256)
pack2_kernel(const int* __restrict__ xs, uint32_t* __restrict__ xd, int nx,
             const int* __restrict__ ws, uint32_t* __restrict__ wd, int nw)
{
    int i = blockIdx.x * blockDim.x + threadIdx.x;
    if (i < nx) {
        int4 v = ((const int4*)xs)[i];
        xd[i] = (v.x & 0xff) | ((v.y & 0xff) << 8) |
                ((v.z & 0xff) << 16) | ((uint32_t)v.w << 24);
    } else if (i < nx + nw) {
        int j = i - nx;
        int4 v = ((const int4*)ws)[j];
        wd[j] = (v.x & 0xff) | ((v.y & 0xff) << 8) |
                ((v.z & 0xff) << 16) | ((uint32_t)v.w << 24);
    }
}

// ---------------- helpers ----------------
__device__ __forceinline__ uint32_t smem_u32(const void* p) {
    return (uint32_t)__cvta_generic_to_shared(p);
}
__device__ __forceinline__ void cp_async16(uint32_t s, const void* g) {
    asm volatile("cp.async.cg.shared.global [%0], [%1], 16;\n" :: "r"(s), "l"(g) : "memory");
}
__device__ __forceinline__ void ldsm_x4(uint32_t& r0, uint32_t& r1, uint32_t& r2, uint32_t& r3,
                                        uint32_t addr)
{
    asm volatile("ldmatrix.sync.aligned.m8n8.x4.shared.b16 {%0,%1,%2,%3}, [%4];"
                 : "=r"(r0), "=r"(r1), "=r"(r2), "=r"(r3) : "r"(addr));
}
#define BAR_T() asm volatile("bar.sync 1, 256;" ::: "memory")
#define BAR_S() asm volatile("bar.sync 2, 256;" ::: "memory")
#define CP_COMMIT() asm volatile("cp.async.commit_group;\n" ::: "memory")
#define CP_WAIT1() asm volatile("cp.async.wait_group 1;\n" ::: "memory")
#define CP_WAIT0() asm volatile("cp.async.wait_group 0;\n" ::: "memory")

__device__ __forceinline__ float quantize_gelu(int acc, float biasv, float a, float b) {
    float y = fmaf(a, (float)acc, biasv);
    float g = 0.5f * y * (1.0f + erff(y * 0.70710678118654752440f));  // exact GeLU
    int q = __float2int_rn(g * b);                                    // rint (RNE)
    q = max(-128, min(127, q));
    return (float)q;
}

// ---------------- hybrid GEMM: decoupled IMMA + DP4A, 3-stage, 1 bar/stage ----
__global__ void __launch_bounds__(THREADS, 1)
w8a8_hybrid_kernel(const float* __restrict__ bias,
                   const float* __restrict__ pa,
                   const float* __restrict__ pb,
                   float* __restrict__ out)
{
    extern __shared__ __align__(16) int8_t smem[];
    const uint32_t sbase = smem_u32(smem);

    const int tid  = threadIdx.x;
    const int lane = tid & 31;
    const int warp = tid >> 5;
    const int bm = blockIdx.y;
    const int bn = blockIdx.x;

    const float a = *pa;
    const float b = *pb;

    const int8_t* gB = g_packedW + (size_t)(bn * BN) * IN_F;

    if (warp < 8) {
        // ================= TENSOR class: rows 0..127 =================
        const int ttid = tid;                     // 0..255
        const int warp_m = (warp >> 2) & 1;       // 64 rows each
        const int warp_n = warp & 3;
        const int quad = lane >> 3;
        const int qr   = lane & 7;
        const int qlow = quad & 1;
        const int qhi  = quad >> 1;

        const int8_t* gA = g_packedX + (size_t)(bm * BM) * IN_F;

        uint32_t aAddr[4], bAddr[2];
#pragma unroll
        for (int i = 0; i < 4; i++) {
            int row = warp_m * 64 + i * 16 + qlow * 8 + qr;
            aAddr[i] = sbase + row * SSTRIDE + qhi * 16;
        }
#pragma unroll
        for (int jj = 0; jj < 2; jj++) {
            int row = warp_n * 32 + jj * 16 + qlow * 8 + qr;
            bAddr[jj] = sbase + T_A + row * SSTRIDE + qhi * 16;
        }

        int acc[4][4][4];
#pragma unroll
        for (int i = 0; i < 4; i++)
#pragma unroll
            for (int j = 0; j < 4; j++)
#pragma unroll
                for (int r = 0; r < 4; r++) acc[i][j][r] = 0;

        auto load_t = [&](int slot, int kt) {
            const int k0 = kt * BK;
            const uint32_t aB = sbase + slot * T_STAGE;
            const uint32_t bB = aB + T_A;
#pragma unroll
            for (int t = 0; t < 4; t++) {            // A: 1024 chunks (128 rows x 8)
                int id = ttid + t * 256;
                int row = id >> 3, c = id & 7;
                cp_async16(aB + row * SSTRIDE + c * 16,
                           gA + (size_t)row * IN_F + k0 + c * 16);
            }
#pragma unroll
            for (int t = 0; t < 4; t++) {            // B: 1024 chunks
                int id = ttid + t * 256;
                int row = id >> 3, c = id & 7;
                cp_async16(bB + row * SSTRIDE + c * 16,
                           gB + (size_t)row * IN_F + k0 + c * 16);
            }
            CP_COMMIT();
        };

        load_t(0, 0);
        load_t(1, 1);

        for (int kt = 0; kt < NK; kt++) {
            if (kt < NK - 1) CP_WAIT1(); else CP_WAIT0();
            BAR_T();

            const uint32_t stageOff = (uint32_t)(kt % NSTAGE) * T_STAGE;
#pragma unroll
            for (int ks = 0; ks < 4; ks++) {
                const uint32_t kOff = stageOff + ks * 32;
                uint32_t b0[4], b1[4];
                ldsm_x4(b0[0], b0[1], b0[2], b0[3], bAddr[0] + kOff);
                ldsm_x4(b1[0], b1[1], b1[2], b1[3], bAddr[1] + kOff);
                uint32_t bf[4][2] = {
                    { b0[0], b0[2] }, { b0[1], b0[3] },
                    { b1[0], b1[2] }, { b1[1], b1[3] }
                };
#pragma unroll
                for (int i = 0; i < 4; i++) {
                    uint32_t a0, a1, a2, a3;
                    ldsm_x4(a0, a1, a2, a3, aAddr[i] + kOff);
#pragma unroll
                    for (int j = 0; j < 4; j++) {
                        asm volatile(
                            "mma.sync.aligned.m16n8k32.row.col.s32.s8.s8.s32 "
                            "{%0,%1,%2,%3}, {%4,%5,%6,%7}, {%8,%9}, {%0,%1,%2,%3};\n"
                            : "+r"(acc[i][j][0]), "+r"(acc[i][j][1]),
                              "+r"(acc[i][j][2]), "+r"(acc[i][j][3])
                            : "r"(a0), "r"(a1), "r"(a2), "r"(a3),
                              "r"(bf[j][0]), "r"(bf[j][1]));
                    }
                }
            }
            if (kt + 2 < NK) load_t((kt + 2) % NSTAGE, kt + 2);
        }

        // tensor epilogue
        const int row_base = bm * BM + warp_m * 64 + (lane >> 2);
        const int col_base = bn * BN + warp_n * 32 + (lane & 3) * 2;
#pragma unroll
        for (int i = 0; i < 4; i++) {
            const int row0 = row_base + i * 16;
#pragma unroll
            for (int j = 0; j < 4; j++) {
                const int col = col_base + j * 8;
                const float b0v = bias[col];
                const float b1v = bias[col + 1];
                float2 v0;
                v0.x = quantize_gelu(acc[i][j][0], b0v, a, b);
                v0.y = quantize_gelu(acc[i][j][1], b1v, a, b);
                *(float2*)&out[(size_t)row0 * OUT_F + col] = v0;
                float2 v1;
                v1.x = quantize_gelu(acc[i][j][2], b0v, a, b);
                v1.y = quantize_gelu(acc[i][j][3], b1v, a, b);
                *(float2*)&out[(size_t)(row0 + 8) * OUT_F + col] = v1;
            }
        }
    } else {
        // ================= SIMT class: rows 128..255 =================
        const int stid = tid - 256;               // 0..255
        const int tm = stid & 15;                 // row offset, stride 16 (8 tiles)
        const int tn = stid >> 4;                 // col offset, stride 16 (8 tiles)

        const int8_t* gA = g_packedX + (size_t)(bm * BM + RT) * IN_F;

        int acc[8][8];
#pragma unroll
        for (int r = 0; r < 8; r++)
#pragma unroll
            for (int c = 0; c < 8; c++) acc[r][c] = 0;

        auto load_s = [&](int slot, int kt) {
            const int k0 = kt * BK;
            const uint32_t aB = sbase + SIMT_BASE + slot * S_STAGE;
            const uint32_t bB = aB + S_A;
#pragma unroll
            for (int t = 0; t < 4; t++) {            // A: 1024 chunks (128 rows x 8)
                int id = stid + t * 256;
                int row = id >> 3, c = id & 7;
                cp_async16(aB + row * SSTRIDE + c * 16,
                           gA + (size_t)row * IN_F + k0 + c * 16);
            }
#pragma unroll
            for (int t = 0; t < 4; t++) {            // B: 1024 chunks
                int id = stid + t * 256;
                int row = id >> 3, c = id & 7;
                cp_async16(bB + row * SSTRIDE + c * 16,
                           gB + (size_t)row * IN_F + k0 + c * 16);
            }
            CP_COMMIT();
        };

        load_s(0, 0);
        load_s(1, 1);

        for (int kt = 0; kt < NK; kt++) {
            if (kt < NK - 1) CP_WAIT1(); else CP_WAIT0();
            BAR_S();

            const int8_t* sA = smem + SIMT_BASE + (kt % NSTAGE) * S_STAGE;
            const int8_t* sB = sA + S_A;
#pragma unroll
            for (int kp = 0; kp < 16; kp++) {
                int2 Bw[8];
#pragma unroll
                for (int c = 0; c < 8; c++)
                    Bw[c] = *(const int2*)(sB + (tn + 16 * c) * SSTRIDE + kp * 8);
#pragma unroll
                for (int r = 0; r < 8; r++) {
                    int2 Aw = *(const int2*)(sA + (tm + 16 * r) * SSTRIDE + kp * 8);
#pragma unroll
                    for (int c = 0; c < 8; c++) {
                        acc[r][c] = __dp4a(Aw.x, Bw[c].x, acc[r][c]);
                        acc[r][c] = __dp4a(Aw.y, Bw[c].y, acc[r][c]);
                    }
                }
            }
            if (kt + 2 < NK) load_s((kt + 2) % NSTAGE, kt + 2);
        }

        // simt epilogue: quantize to smem staging, then coalesced stores
        BAR_S();     // all simt warps done with stage buffers before reuse as staging
        float* epi = (float*)(smem + SIMT_BASE);
#pragma unroll
        for (int r = 0; r < 8; r++) {
            const int srow = tm + 16 * r;
#pragma unroll
            for (int c = 0; c < 8; c++) {
                const int scol = tn + 16 * c;
                const float bv = bias[bn * BN + scol];
                epi[srow * EPI_ROW_WORDS + scol] = quantize_gelu(acc[r][c], bv, a, b);
            }
        }
        BAR_S();

        // 128 rows x 32 float4 = 4096 stores over 256 threads = 16 each
#pragma unroll
        for (int t = 0; t < 16; t++) {
            int idx = stid + t * 256;
            int row = idx >> 5;
            int c4  = idx & 31;
            const float* s = &epi[row * EPI_ROW_WORDS + c4 * 4];
            float4 v = make_float4(s[0], s[1], s[2], s[3]);
            *(float4*)&out[(size_t)(bm * BM + RT + row) * OUT_F + bn * BN + c4 * 4] = v;
        }
    }
}

extern "C" void kernel_launch(void* const* d_in, const int* in_sizes, int n_in,
                              void* d_out, int out_size)
{
    const int*   x    = (const int*)  d_in[0];   // int32-widened int8 values
    const int*   w    = (const int*)  d_in[1];
    const float* bias = (const float*)d_in[2];
    const float* a    = (const float*)d_in[3];
    const float* b    = (const float*)d_in[4];
    float* out = (float*)d_out;

    int8_t* pX = nullptr;
    int8_t* pW = nullptr;
    cudaGetSymbolAddress((void**)&pX, g_packedX);
    cudaGetSymbolAddress((void**)&pW, g_packedW);

    {
        // fused single launch; EXPLICIT per-array packed-word counts
        const int nx = (TOKENS * IN_F) / 4;   // 8,388,608
        const int nw = (OUT_F * IN_F) / 4;    // 4,194,304
        const int total = nx + nw;
        pack2_kernel<<<(total + 255) / 256, 256>>>(
            x, (uint32_t*)pX, nx, w, (uint32_t*)pW, nw);
    }

    cudaFuncSetAttribute(w8a8_hybrid_kernel,
                         cudaFuncAttributeMaxDynamicSharedMemorySize, SMEM_TOTAL);
    dim3 grid(OUT_F / BN, TOKENS / BM);   // (32, 32)
    w8a8_hybrid_kernel<<<grid, THREADS, SMEM_TOTAL>>>(bias, a, b, out);
}